// round 1
// baseline (speedup 1.0000x reference)
#include <cuda_runtime.h>
#include <cuda_bf16.h>
#include <math.h>

// Problem constants
#define BATCH 8
#define TLEN  4096
#define NGRP  8
#define NCODE 1024
#define DGRP  64
#define DMODEL 512

// ---------------- scratch (device globals; no allocs allowed) ----------------
__device__ float g_x1[BATCH * 64  * TLEN];
__device__ float g_x2[BATCH * 128 * TLEN];
__device__ float g_x3[BATCH * 256 * TLEN];
__device__ float g_x4[BATCH * 512 * TLEN];
__device__ float g_x5[BATCH * 512 * TLEN];
__device__ int   g_idx[BATCH * NGRP * TLEN];
__device__ float g_cnorm[NGRP * NCODE];
__device__ float g_pc[NGRP * NCODE * 256];   // precomputed per-code head logits

// ---------------- conv1: 1 -> 64, k=7, ELU ----------------
__global__ void conv1_k(const float* __restrict__ a,
                        const float* __restrict__ w1,
                        const float* __restrict__ b1,
                        float* __restrict__ y)
{
    __shared__ float sw[64 * 7];
    __shared__ float sb[64];
    int tid = threadIdx.x;
    for (int i = tid; i < 64 * 7; i += 256) sw[i] = w1[i];
    if (tid < 64) sb[tid] = b1[tid];
    __syncthreads();

    int t = blockIdx.x * 256 + tid;
    int b = blockIdx.y;
    float xr[7];
#pragma unroll
    for (int k = 0; k < 7; k++) {
        int tt = t - 6 + k;
        xr[k] = (tt >= 0) ? a[b * TLEN + tt] : 0.f;
    }
#pragma unroll 4
    for (int o = 0; o < 64; o++) {
        float acc = sb[o];
#pragma unroll
        for (int k = 0; k < 7; k++) acc += sw[o * 7 + k] * xr[k];
        acc = (acc > 0.f) ? acc : expm1f(acc);
        y[((size_t)b * 64 + o) * TLEN + t] = acc;
    }
}

// ---------------- generic causal conv: Cin -> Cout, kernel K ----------------
// Tile: 128 output channels x 64 time steps per block, 128 threads,
// per-thread register tile 8 o x 8 t. Smem-staged x window + weights.
template<int K, int DO_ELU>
__global__ void __launch_bounds__(128)
conv_k(const float* __restrict__ x, const float* __restrict__ w,
       const float* __restrict__ bias, float* __restrict__ y,
       int Cin, int Cout)
{
    constexpr int TT = 64, OT = 128, CC = 8;
    constexpr int XW = TT + K - 1;
    constexpr int WR = CC * K + 1;          // padded row: kills 4-way bank conflict
    __shared__ float sx[CC][XW];
    __shared__ float sw[OT][WR];

    int tid = threadIdx.x;
    int tg = tid & 7;          // 8 t-groups of 8
    int og = tid >> 3;         // 16 o-groups of 8
    int t0 = blockIdx.x * TT;
    int o0 = blockIdx.y * OT;
    int b  = blockIdx.z;

    float acc[8][8];
#pragma unroll
    for (int o = 0; o < 8; o++)
#pragma unroll
        for (int t = 0; t < 8; t++) acc[o][t] = 0.f;

    const float* xb = x + (size_t)b * Cin * TLEN;

    for (int c0 = 0; c0 < Cin; c0 += CC) {
        for (int i = tid; i < CC * XW; i += 128) {
            int c = i / XW, tt = i % XW;
            int t = t0 + tt - (K - 1);
            sx[c][tt] = (t >= 0) ? xb[(size_t)(c0 + c) * TLEN + t] : 0.f;
        }
        for (int i = tid; i < OT * CC * K; i += 128) {
            int o = i / (CC * K), r = i % (CC * K);
            sw[o][r] = w[(size_t)(o0 + o) * Cin * K + c0 * K + r];
        }
        __syncthreads();

#pragma unroll
        for (int c = 0; c < CC; c++) {
            float xr[8 + K - 1];
#pragma unroll
            for (int j = 0; j < 8 + K - 1; j++) xr[j] = sx[c][tg * 8 + j];
#pragma unroll
            for (int k = 0; k < K; k++) {
#pragma unroll
                for (int o = 0; o < 8; o++) {
                    float wv = sw[og * 8 + o][c * K + k];
#pragma unroll
                    for (int t = 0; t < 8; t++)
                        acc[o][t] += wv * xr[t + k];
                }
            }
        }
        __syncthreads();
    }

#pragma unroll
    for (int o = 0; o < 8; o++) {
        int oo = o0 + og * 8 + o;
        float bv = bias[oo];
        float* yo = y + ((size_t)b * Cout + oo) * TLEN + t0 + tg * 8;
#pragma unroll
        for (int t = 0; t < 8; t++) {
            float v = acc[o][t] + bv;
            if (DO_ELU) v = (v > 0.f) ? v : expm1f(v);
            yo[t] = v;
        }
    }
}

// ---------------- codebook norms + zero vq slot ----------------
__global__ void cnorm_k(const float* __restrict__ cb, float* __restrict__ out_vq)
{
    int i = blockIdx.x * 256 + threadIdx.x;   // 8192 codes total
    if (i == 0) out_vq[0] = 0.f;
    const float4* c4 = (const float4*)(cb + (size_t)i * DGRP);
    float s = 0.f;
#pragma unroll
    for (int j = 0; j < 16; j++) {
        float4 v = c4[j];
        s += v.x * v.x + v.y * v.y + v.z * v.z + v.w * v.w;
    }
    g_cnorm[i] = s;
}

// ---------------- precompute per-code head logits ----------------
// pc[g][k][h*64+v] = sum_d cb[g][k][d] * head_w[h][g*64+d][v]
__global__ void pc_k(const float* __restrict__ cb, const float* __restrict__ hw)
{
    __shared__ float sc[DGRP];
    int gk = blockIdx.x;                 // g*1024 + k
    int g = gk >> 10;
    int tid = threadIdx.x;               // hv in [0,256)
    if (tid < DGRP) sc[tid] = cb[(size_t)gk * DGRP + tid];
    __syncthreads();
    int h = tid >> 6, v = tid & 63;
    const float* wp = hw + (size_t)h * DMODEL * 64 + (size_t)(g * DGRP) * 64 + v;
    float acc = 0.f;
#pragma unroll
    for (int d = 0; d < DGRP; d++) acc += sc[d] * wp[d * 64];
    g_pc[(size_t)gk * 256 + tid] = acc;
}

// ---------------- VQ: argmin over 1024 codes per (b,t,g) ----------------
__global__ void __launch_bounds__(256)
vq_k(const float* __restrict__ x5, const float* __restrict__ cb,
     float* __restrict__ outA, float* __restrict__ out_vq)
{
    constexpr int TTILE = 32;
    __shared__ float sz[TTILE][DGRP];
    __shared__ float sdist[TTILE][8];
    __shared__ int   skidx[TTILE][8];
    __shared__ float szn[TTILE];

    int tid = threadIdx.x;
    int t0 = blockIdx.x * TTILE;
    int g  = blockIdx.y;
    int b  = blockIdx.z;

    const float* xp = x5 + ((size_t)b * DMODEL + g * DGRP) * TLEN + t0;
    for (int i = tid; i < TTILE * DGRP; i += 256) {
        int d = i >> 5, tt = i & 31;
        sz[tt][d] = xp[(size_t)d * TLEN + tt];
    }
    __syncthreads();

    int tl = tid >> 3, cg = tid & 7;
    float z[DGRP];
    float zn = 0.f;
#pragma unroll
    for (int d = 0; d < DGRP; d++) { z[d] = sz[tl][d]; zn += z[d] * z[d]; }

    float best = 3.0e38f;
    int bi = 0;
    const float4* cb4 = (const float4*)(cb + (size_t)g * NCODE * DGRP);
    const float* cn = g_cnorm + g * NCODE;
    for (int k = cg; k < NCODE; k += 8) {
        const float4* c4 = cb4 + k * 16;
        float dot = 0.f;
#pragma unroll
        for (int j = 0; j < 16; j++) {
            float4 v = c4[j];
            dot += z[4*j] * v.x + z[4*j+1] * v.y + z[4*j+2] * v.z + z[4*j+3] * v.w;
        }
        float dist = cn[k] - 2.f * dot;
        if (dist < best) { best = dist; bi = k; }
    }
    sdist[tl][cg] = best;
    skidx[tl][cg] = bi;
    if (cg == 0) szn[tl] = zn;
    __syncthreads();

    if (tid < TTILE) {
        int tt = tid;
        float bd = sdist[tt][0];
        int bk = skidx[tt][0];
#pragma unroll
        for (int j = 1; j < 8; j++) {
            float d = sdist[tt][j]; int kk = skidx[tt][j];
            if (d < bd || (d == bd && kk < bk)) { bd = d; bk = kk; }
        }
        size_t ai = ((size_t)b * NGRP + g) * TLEN + t0 + tt;
        g_idx[ai] = bk;
        outA[ai] = (float)bk;
        float md = szn[tt] + bd;           // = ||z - c_best||^2
#pragma unroll
        for (int off = 16; off; off >>= 1)
            md += __shfl_down_sync(0xffffffffu, md, off);
        if (tid == 0)
            atomicAdd(out_vq, md * (1.f / (float)(BATCH * TLEN * DGRP)));
    }
}

// ---------------- head: gather precomputed per-code logits ----------------
__global__ void __launch_bounds__(256)
head_k(const float* __restrict__ hb, float* __restrict__ outB)
{
    constexpr int TTILE = 32;
    __shared__ int sidx[TTILE][8];
    int tid = threadIdx.x;
    int b = blockIdx.y;
    int t0 = blockIdx.x * TTILE;
    {
        int tt = tid >> 3, g = tid & 7;
        sidx[tt][g] = g_idx[((size_t)b * NGRP + g) * TLEN + t0 + tt];
    }
    __syncthreads();

    int hv = tid;
    float bias = hb[hv];
    int h = hv >> 6, v = hv & 63;
    for (int tt = 0; tt < TTILE; tt++) {
        float acc = bias;
#pragma unroll
        for (int g = 0; g < 8; g++) {
            int k = sidx[tt][g];
            acc += g_pc[((size_t)(g * NCODE + k)) * 256 + hv];
        }
        outB[(((size_t)b * 4 + h) * TLEN + (t0 + tt)) * 64 + v] = acc;
    }
}

// ---------------- launch ----------------
extern "C" void kernel_launch(void* const* d_in, const int* in_sizes, int n_in,
                              void* d_out, int out_size)
{
    const float* audio = (const float*)d_in[0];
    const float* w1 = (const float*)d_in[1];
    const float* b1 = (const float*)d_in[2];
    const float* w2 = (const float*)d_in[3];
    const float* b2 = (const float*)d_in[4];
    const float* w3 = (const float*)d_in[5];
    const float* b3 = (const float*)d_in[6];
    const float* w4 = (const float*)d_in[7];
    const float* b4 = (const float*)d_in[8];
    const float* w5 = (const float*)d_in[9];
    const float* b5 = (const float*)d_in[10];
    const float* cb = (const float*)d_in[11];
    const float* hw = (const float*)d_in[12];
    const float* hb = (const float*)d_in[13];

    float* out  = (float*)d_out;
    float* outA = out;                                        // a_tokens: 8*8*4096
    float* outB = out + (size_t)BATCH * NGRP * TLEN;          // b_logits: 8*4*4096*64
    float* outV = outB + (size_t)BATCH * 4 * TLEN * 64;       // vq_loss scalar

    cnorm_k<<<NGRP * NCODE / 256, 256>>>(cb, outV);
    pc_k<<<NGRP * NCODE, 256>>>(cb, hw);

    conv1_k<<<dim3(TLEN / 256, BATCH), 256>>>(audio, w1, b1, g_x1);
    conv_k<5, 1><<<dim3(TLEN / 64, 128 / 128, BATCH), 128>>>(g_x1, w2, b2, g_x2, 64, 128);
    conv_k<5, 1><<<dim3(TLEN / 64, 256 / 128, BATCH), 128>>>(g_x2, w3, b3, g_x3, 128, 256);
    conv_k<3, 1><<<dim3(TLEN / 64, 512 / 128, BATCH), 128>>>(g_x3, w4, b4, g_x4, 256, 512);
    conv_k<3, 0><<<dim3(TLEN / 64, 512 / 128, BATCH), 128>>>(g_x4, w5, b5, g_x5, 512, 512);

    vq_k<<<dim3(TLEN / 32, NGRP, BATCH), 256>>>(g_x5, cb, outA, outV);
    head_k<<<dim3(TLEN / 32, BATCH), 256>>>(hb, outB);
}

// round 6
// speedup vs baseline: 1.4844x; 1.4844x over previous
#include <cuda_runtime.h>
#include <cuda_bf16.h>
#include <math.h>
#include <stdint.h>

// Problem constants
#define BATCH 8
#define TLEN  4096
#define NGRP  8
#define NCODE 1024
#define DGRP  64
#define DMODEL 512

// ---------------- f32x2 packed-math macros ----------------
#define FMA_F32X2(d, a, b, c) \
    asm("fma.rn.f32x2 %0, %1, %2, %3;" : "=l"(d) : "l"(a), "l"(b), "l"(c))
// float-typed unpack: 'f' constraint for fp32 registers
#define UNPACK_F32X2F(lo, hi, in) \
    asm("mov.b64 {%0, %1}, %2;" : "=f"(lo), "=f"(hi) : "l"(in))

__device__ __forceinline__ uint64_t pack2f(float a, float b) {
    uint64_t r;
    asm("mov.b64 %0, {%1, %2};" : "=l"(r) : "f"(a), "f"(b));
    return r;
}

// cp.async 4B with zero-fill option
__device__ __forceinline__ void cpa4(uint32_t dst, const float* src, bool valid) {
    if (valid)
        asm volatile("cp.async.ca.shared.global [%0], [%1], 4;\n" :: "r"(dst), "l"(src));
    else
        asm volatile("cp.async.ca.shared.global [%0], [%1], 4, 0;\n" :: "r"(dst), "l"(src));
}
__device__ __forceinline__ uint32_t s2u(const void* p) {
    uint32_t a;
    asm("{ .reg .u64 t; cvta.to.shared.u64 t, %1; cvt.u32.u64 %0, t; }" : "=r"(a) : "l"(p));
    return a;
}

// ---------------- scratch ----------------
__device__ float g_x1[BATCH * 64  * TLEN];
__device__ float g_x2[BATCH * 128 * TLEN];
__device__ float g_x3[BATCH * 256 * TLEN];
__device__ float g_x4[BATCH * 512 * TLEN];
__device__ float g_x5[BATCH * 512 * TLEN];
__device__ int   g_idx[BATCH * NGRP * TLEN];
__device__ float g_cnorm[NGRP * NCODE];
__device__ float g_pc[NGRP * NCODE * 256];

// ---------------- conv1: 1 -> 64, k=7, ELU ----------------
__global__ void conv1_k(const float* __restrict__ a,
                        const float* __restrict__ w1,
                        const float* __restrict__ b1,
                        float* __restrict__ y)
{
    __shared__ float sw[64 * 7];
    __shared__ float sb[64];
    int tid = threadIdx.x;
    for (int i = tid; i < 64 * 7; i += 256) sw[i] = w1[i];
    if (tid < 64) sb[tid] = b1[tid];
    __syncthreads();

    int t = blockIdx.x * 256 + tid;
    int b = blockIdx.y;
    float xr[7];
#pragma unroll
    for (int k = 0; k < 7; k++) {
        int tt = t - 6 + k;
        xr[k] = (tt >= 0) ? a[b * TLEN + tt] : 0.f;
    }
#pragma unroll 4
    for (int o = 0; o < 64; o++) {
        float acc = sb[o];
#pragma unroll
        for (int k = 0; k < 7; k++) acc += sw[o * 7 + k] * xr[k];
        acc = (acc > 0.f) ? acc : expm1f(acc);
        y[((size_t)b * 64 + o) * TLEN + t] = acc;
    }
}

// ---------------- generic causal conv, f32x2 + cp.async double-buffer ----------
// Tile: OT out-channels x 128 timesteps, 256 threads.
// Per-thread: OPT(=OT/16) o x 8 t register tile, o packed in f32x2 pairs.
template<int K, int DO_ELU, int OT>
__global__ void __launch_bounds__(256, 2)
conv_k(const float* __restrict__ x, const float* __restrict__ w,
       const float* __restrict__ bias, float* __restrict__ y,
       int Cin, int Cout)
{
    constexpr int TT = 128, CC = 8;
    constexpr int OPT = OT / 16;           // 8 (OT=128) or 4 (OT=64)
    constexpr int OP2 = OPT / 2;
    constexpr int XW  = TT + K - 1;
    constexpr int XWP = (XW + 3) & ~3;     // pad rows to 16B multiple
    constexpr int OTP = OT + 2;            // pad weight rows (even, 8B-aligned pairs)
    constexpr int WCHUNK = CC * K;         // 24 or 40

    __shared__ float sx[2][CC][XWP];
    __shared__ float sw[2][WCHUNK][OTP];

    int tid = threadIdx.x;
    int tg = tid & 15;                     // 16 t-groups of 8
    int og = tid >> 4;                     // 16 o-groups of OPT
    int t0 = blockIdx.x * TT;
    int o0 = blockIdx.y * OT;
    int b  = blockIdx.z;

    const float* xb = x + (size_t)b * Cin * TLEN;
    const int nIter = Cin / CC;

    // async stage of channel-chunk ci into buffer p
    auto load_chunk = [&](int ci, int p) {
        int c0 = ci * CC;
        // x rows
        for (int i = tid; i < CC * XW; i += 256) {
            int c = i / XW, tt = i % XW;
            int t = t0 + tt - (K - 1);
            cpa4(s2u(&sx[p][c][tt]), xb + (size_t)(c0 + c) * TLEN + t, t >= 0);
        }
        // weights: global [o][Cin*K], chunk is 8K contiguous per o at offset c0*K
        for (int i = tid; i < OT * WCHUNK; i += 256) {
            int o = i / WCHUNK, r = i % WCHUNK;
            cpa4(s2u(&sw[p][r][o]),
                 w + (size_t)(o0 + o) * Cin * K + c0 * K + r, true);
        }
    };

    uint64_t acc2[OP2][8];
#pragma unroll
    for (int o = 0; o < OP2; o++)
#pragma unroll
        for (int t = 0; t < 8; t++) acc2[o][t] = 0ull;

    load_chunk(0, 0);
    asm volatile("cp.async.commit_group;");

    for (int it = 0; it < nIter; ++it) {
        int p = it & 1;
        if (it + 1 < nIter) {
            load_chunk(it + 1, p ^ 1);
            asm volatile("cp.async.commit_group;");
            asm volatile("cp.async.wait_group 1;");
        } else {
            asm volatile("cp.async.wait_group 0;");
        }
        __syncthreads();

#pragma unroll
        for (int c = 0; c < CC; c++) {
            // load 8+K-1 x values (vectorized head), duplicate into f32x2
            float xs[8 + K - 1];
            {
                const float4* xr4 = (const float4*)&sx[p][c][tg * 8];
                float4 v0 = xr4[0], v1 = xr4[1];
                xs[0] = v0.x; xs[1] = v0.y; xs[2] = v0.z; xs[3] = v0.w;
                xs[4] = v1.x; xs[5] = v1.y; xs[6] = v1.z; xs[7] = v1.w;
#pragma unroll
                for (int j = 0; j < K - 1; j++) xs[8 + j] = sx[p][c][tg * 8 + 8 + j];
            }
            uint64_t xx[8 + K - 1];
#pragma unroll
            for (int j = 0; j < 8 + K - 1; j++) xx[j] = pack2f(xs[j], xs[j]);

#pragma unroll
            for (int k = 0; k < K; k++) {
#pragma unroll
                for (int o2 = 0; o2 < OP2; o2++) {
                    uint64_t wv2 = *(const uint64_t*)&sw[p][c * K + k][og * OPT + 2 * o2];
#pragma unroll
                    for (int t = 0; t < 8; t++)
                        FMA_F32X2(acc2[o2][t], wv2, xx[t + k], acc2[o2][t]);
                }
            }
        }
        __syncthreads();
    }

    // epilogue
#pragma unroll
    for (int o2 = 0; o2 < OP2; o2++) {
        int oo0 = o0 + og * OPT + 2 * o2;
        float b0 = bias[oo0], b1 = bias[oo0 + 1];
        float r0[8], r1[8];
#pragma unroll
        for (int t = 0; t < 8; t++) {
            float lo, hi;
            UNPACK_F32X2F(lo, hi, acc2[o2][t]);
            lo += b0; hi += b1;
            if (DO_ELU) {
                lo = (lo > 0.f) ? lo : expm1f(lo);
                hi = (hi > 0.f) ? hi : expm1f(hi);
            }
            r0[t] = lo; r1[t] = hi;
        }
        float4* y0 = (float4*)(y + ((size_t)b * Cout + oo0) * TLEN + t0 + tg * 8);
        float4* y1 = (float4*)(y + ((size_t)b * Cout + oo0 + 1) * TLEN + t0 + tg * 8);
        y0[0] = make_float4(r0[0], r0[1], r0[2], r0[3]);
        y0[1] = make_float4(r0[4], r0[5], r0[6], r0[7]);
        y1[0] = make_float4(r1[0], r1[1], r1[2], r1[3]);
        y1[1] = make_float4(r1[4], r1[5], r1[6], r1[7]);
    }
}

// ---------------- codebook norms + zero vq slot ----------------
__global__ void cnorm_k(const float* __restrict__ cb, float* __restrict__ out_vq)
{
    int i = blockIdx.x * 256 + threadIdx.x;
    if (i == 0) out_vq[0] = 0.f;
    const float4* c4 = (const float4*)(cb + (size_t)i * DGRP);
    float s = 0.f;
#pragma unroll
    for (int j = 0; j < 16; j++) {
        float4 v = c4[j];
        s += v.x * v.x + v.y * v.y + v.z * v.z + v.w * v.w;
    }
    g_cnorm[i] = s;
}

// ---------------- precompute per-code head logits ----------------
__global__ void pc_k(const float* __restrict__ cb, const float* __restrict__ hw)
{
    __shared__ float sc[DGRP];
    int gk = blockIdx.x;
    int g = gk >> 10;
    int tid = threadIdx.x;
    if (tid < DGRP) sc[tid] = cb[(size_t)gk * DGRP + tid];
    __syncthreads();
    int h = tid >> 6, v = tid & 63;
    const float* wp = hw + (size_t)h * DMODEL * 64 + (size_t)(g * DGRP) * 64 + v;
    float acc = 0.f;
#pragma unroll
    for (int d = 0; d < DGRP; d++) acc += sc[d] * wp[d * 64];
    g_pc[(size_t)gk * 256 + tid] = acc;
}

// ---------------- VQ: argmin over 1024 codes per (b,t,g), f32x2 dot ----------
__global__ void __launch_bounds__(256)
vq_k(const float* __restrict__ x5, const float* __restrict__ cb,
     float* __restrict__ outA, float* __restrict__ out_vq)
{
    constexpr int TTILE = 32;
    __shared__ float sz[TTILE][DGRP];
    __shared__ float sdist[TTILE][8];
    __shared__ int   skidx[TTILE][8];
    __shared__ float szn[TTILE];

    int tid = threadIdx.x;
    int t0 = blockIdx.x * TTILE;
    int g  = blockIdx.y;
    int b  = blockIdx.z;

    const float* xp = x5 + ((size_t)b * DMODEL + g * DGRP) * TLEN + t0;
    for (int i = tid; i < TTILE * DGRP; i += 256) {
        int d = i >> 5, tt = i & 31;
        sz[tt][d] = xp[(size_t)d * TLEN + tt];
    }
    __syncthreads();

    int tl = tid >> 3, cg = tid & 7;

    uint64_t z2[DGRP / 2];
    {
        const uint64_t* zp = (const uint64_t*)sz[tl];
#pragma unroll
        for (int j = 0; j < DGRP / 2; j++) z2[j] = zp[j];
    }
    // ||z||^2 via packed FMA
    float zn;
    {
        uint64_t a = 0;
#pragma unroll
        for (int j = 0; j < DGRP / 2; j++) FMA_F32X2(a, z2[j], z2[j], a);
        float lo, hi; UNPACK_F32X2F(lo, hi, a);
        zn = lo + hi;
    }

    float best = 3.0e38f;
    int bi = 0;
    const float4* cb4 = (const float4*)(cb + (size_t)g * NCODE * DGRP);
    const float* cn = g_cnorm + g * NCODE;
#pragma unroll 2
    for (int k = cg; k < NCODE; k += 8) {
        const float4* c4 = cb4 + k * 16;
        uint64_t d2 = 0;
#pragma unroll
        for (int j = 0; j < 16; j++) {
            float4 v = c4[j];
            uint64_t lo = pack2f(v.x, v.y);
            uint64_t hi = pack2f(v.z, v.w);
            FMA_F32X2(d2, lo, z2[2 * j], d2);
            FMA_F32X2(d2, hi, z2[2 * j + 1], d2);
        }
        float dl, dh; UNPACK_F32X2F(dl, dh, d2);
        float dist = cn[k] - 2.f * (dl + dh);
        if (dist < best) { best = dist; bi = k; }
    }
    sdist[tl][cg] = best;
    skidx[tl][cg] = bi;
    if (cg == 0) szn[tl] = zn;
    __syncthreads();

    if (tid < TTILE) {
        int tt = tid;
        float bd = sdist[tt][0];
        int bk = skidx[tt][0];
#pragma unroll
        for (int j = 1; j < 8; j++) {
            float d = sdist[tt][j]; int kk = skidx[tt][j];
            if (d < bd || (d == bd && kk < bk)) { bd = d; bk = kk; }
        }
        size_t ai = ((size_t)b * NGRP + g) * TLEN + t0 + tt;
        g_idx[ai] = bk;
        outA[ai] = (float)bk;
        float md = szn[tt] + bd;
#pragma unroll
        for (int off = 16; off; off >>= 1)
            md += __shfl_down_sync(0xffffffffu, md, off);
        if (tid == 0)
            atomicAdd(out_vq, md * (1.f / (float)(BATCH * TLEN * DGRP)));
    }
}

// ---------------- head: gather precomputed per-code logits ----------------
__global__ void __launch_bounds__(256)
head_k(const float* __restrict__ hb, float* __restrict__ outB)
{
    constexpr int TTILE = 32;
    __shared__ int sidx[TTILE][8];
    int tid = threadIdx.x;
    int b = blockIdx.y;
    int t0 = blockIdx.x * TTILE;
    {
        int tt = tid >> 3, g = tid & 7;
        sidx[tt][g] = g_idx[((size_t)b * NGRP + g) * TLEN + t0 + tt];
    }
    __syncthreads();

    int hv = tid;
    float bias = hb[hv];
    int h = hv >> 6, v = hv & 63;
    for (int tt = 0; tt < TTILE; tt++) {
        float acc = bias;
#pragma unroll
        for (int g = 0; g < 8; g++) {
            int k = sidx[tt][g];
            acc += g_pc[((size_t)(g * NCODE + k)) * 256 + hv];
        }
        outB[(((size_t)b * 4 + h) * TLEN + (t0 + tt)) * 64 + v] = acc;
    }
}

// ---------------- launch ----------------
extern "C" void kernel_launch(void* const* d_in, const int* in_sizes, int n_in,
                              void* d_out, int out_size)
{
    const float* audio = (const float*)d_in[0];
    const float* w1 = (const float*)d_in[1];
    const float* b1 = (const float*)d_in[2];
    const float* w2 = (const float*)d_in[3];
    const float* b2 = (const float*)d_in[4];
    const float* w3 = (const float*)d_in[5];
    const float* b3 = (const float*)d_in[6];
    const float* w4 = (const float*)d_in[7];
    const float* b4 = (const float*)d_in[8];
    const float* w5 = (const float*)d_in[9];
    const float* b5 = (const float*)d_in[10];
    const float* cb = (const float*)d_in[11];
    const float* hw = (const float*)d_in[12];
    const float* hb = (const float*)d_in[13];

    float* out  = (float*)d_out;
    float* outA = out;
    float* outB = out + (size_t)BATCH * NGRP * TLEN;
    float* outV = outB + (size_t)BATCH * 4 * TLEN * 64;

    cnorm_k<<<NGRP * NCODE / 256, 256>>>(cb, outV);
    pc_k<<<NGRP * NCODE, 256>>>(cb, hw);

    conv1_k<<<dim3(TLEN / 256, BATCH), 256>>>(audio, w1, b1, g_x1);
    conv_k<5, 1, 64 ><<<dim3(TLEN / 128, 128 / 64,  BATCH), 256>>>(g_x1, w2, b2, g_x2, 64, 128);
    conv_k<5, 1, 64 ><<<dim3(TLEN / 128, 256 / 64,  BATCH), 256>>>(g_x2, w3, b3, g_x3, 128, 256);
    conv_k<3, 1, 128><<<dim3(TLEN / 128, 512 / 128, BATCH), 256>>>(g_x3, w4, b4, g_x4, 256, 512);
    conv_k<3, 0, 128><<<dim3(TLEN / 128, 512 / 128, BATCH), 256>>>(g_x4, w5, b5, g_x5, 512, 512);

    vq_k<<<dim3(TLEN / 32, NGRP, BATCH), 256>>>(g_x5, cb, outA, outV);
    head_k<<<dim3(TLEN / 32, BATCH), 256>>>(hb, outB);
}

// round 14
// speedup vs baseline: 3.4575x; 2.3292x over previous
#include <cuda_runtime.h>
#include <cuda_bf16.h>
#include <math.h>
#include <stdint.h>

#define BATCH 8
#define TLEN  4096
#define NGRP  8
#define NCODE 1024
#define DGRP  64
#define DMODEL 512

typedef unsigned long long u64;

// ---------------- f32x2 packed-math ----------------
#define FMA_F32X2(d, a, b, c) \
    asm("fma.rn.f32x2 %0, %1, %2, %3;" : "=l"(d) : "l"(a), "l"(b), "l"(c))
#define UNPACK_F32X2F(lo, hi, in) \
    asm("mov.b64 {%0, %1}, %2;" : "=f"(lo), "=f"(hi) : "l"(in))

__device__ __forceinline__ u64 pack2f(float a, float b) {
    u64 r;
    asm("mov.b64 %0, {%1, %2};" : "=l"(r) : "f"(a), "f"(b));
    return r;
}

__device__ __forceinline__ void cpa4(uint32_t dst, const float* src) {
    asm volatile("cp.async.ca.shared.global [%0], [%1], 4;\n" :: "r"(dst), "l"(src));
}
__device__ __forceinline__ uint32_t s2u(const void* p) {
    uint32_t a;
    asm("{ .reg .u64 t; cvta.to.shared.u64 t, %1; cvt.u32.u64 %0, t; }" : "=r"(a) : "l"(p));
    return a;
}

// ---------------- scratch ----------------
__device__ float g_x1[BATCH * 64  * TLEN];
__device__ float g_x2[BATCH * 128 * TLEN];
__device__ float g_x3[BATCH * 256 * TLEN];
__device__ float g_x4[BATCH * 512 * TLEN];
__device__ float g_x5[BATCH * 512 * TLEN];
__device__ int   g_idx[BATCH * NGRP * TLEN];
__device__ float g_cnorm[NGRP * NCODE];
__device__ float g_pc[NGRP * NCODE * 256];
__device__ float g_vqpart[(TLEN / 32) * NGRP * BATCH];   // 8192

// ---------------- conv1: 1 -> 64, k=7, ELU ----------------
__global__ void conv1_k(const float* __restrict__ a,
                        const float* __restrict__ w1,
                        const float* __restrict__ b1,
                        float* __restrict__ y)
{
    __shared__ float sw[64 * 7];
    __shared__ float sb[64];
    int tid = threadIdx.x;
    for (int i = tid; i < 64 * 7; i += 256) sw[i] = w1[i];
    if (tid < 64) sb[tid] = b1[tid];
    __syncthreads();

    int t = blockIdx.x * 256 + tid;
    int b = blockIdx.y;
    float xr[7];
#pragma unroll
    for (int k = 0; k < 7; k++) {
        int tt = t - 6 + k;
        xr[k] = (tt >= 0) ? a[b * TLEN + tt] : 0.f;
    }
#pragma unroll 4
    for (int o = 0; o < 64; o++) {
        float acc = sb[o];
#pragma unroll
        for (int k = 0; k < 7; k++) acc += sw[o * 7 + k] * xr[k];
        acc = (acc > 0.f) ? acc : expm1f(acc);
        y[((size_t)b * 64 + o) * TLEN + t] = acc;
    }
}

// ---------------- causal conv: OT=64 out-ch x 128 t, f32x2, dup-x smem --------
// 256 threads: tg = tid&15 (t-lane), og = tid>>4 (16 o-groups of 4).
// Thread's 8 timesteps are STRIDE-16 interleaved: t = tg + 16*j  (conflict-free LDS).
template<int K, int DO_ELU>
__global__ void __launch_bounds__(256, 3)
conv_k(const float* __restrict__ x, const float* __restrict__ w,
       const float* __restrict__ bias, float* __restrict__ y,
       int Cin, int Cout)
{
    constexpr int TT = 128, CC = 8, OT = 64;
    constexpr int XW = TT + K - 1;
    constexpr int OTP = OT + 2;
    constexpr int WCHUNK = CC * K;
    constexpr int NXR = (CC * XW + 255) / 256;   // x elems per thread per chunk

    __shared__ u64   sxd[CC][XW];                 // duplicated x pairs
    __shared__ float swt[2][WCHUNK][OTP];         // weight pairs [r][o]

    int tid = threadIdx.x;
    int tg = tid & 15;
    int og = tid >> 4;
    int t0 = blockIdx.x * TT;
    int o0 = blockIdx.y * OT;
    int b  = blockIdx.z;

    const float* xb = x + (size_t)b * Cin * TLEN;
    const int nIter = Cin / CC;

    auto load_w = [&](int ci, int p) {
        int c0 = ci * CC;
        for (int i = tid; i < OT * WCHUNK; i += 256) {
            int o = i / WCHUNK, r = i % WCHUNK;
            cpa4(s2u(&swt[p][r][o]), w + (size_t)(o0 + o) * Cin * K + c0 * K + r);
        }
        asm volatile("cp.async.commit_group;");
    };

    float xr[NXR];
    auto load_x = [&](int ci) {
        int c0 = ci * CC;
#pragma unroll
        for (int r = 0; r < NXR; r++) {
            int i = tid + r * 256;
            if (i < CC * XW) {
                int c = i / XW, tt = i % XW;
                int t = t0 + tt - (K - 1);
                xr[r] = (t >= 0) ? xb[(size_t)(c0 + c) * TLEN + t] : 0.f;
            }
        }
    };
    auto sts_x = [&]() {
#pragma unroll
        for (int r = 0; r < NXR; r++) {
            int i = tid + r * 256;
            if (i < CC * XW) {
                int c = i / XW, tt = i % XW;
                sxd[c][tt] = pack2f(xr[r], xr[r]);
            }
        }
    };

    u64 acc[2][8];
#pragma unroll
    for (int o2 = 0; o2 < 2; o2++)
#pragma unroll
        for (int j = 0; j < 8; j++) acc[o2][j] = 0ull;

    // prologue: weights depth-2, x chunk 0
    load_w(0, 0);
    if (nIter > 1) load_w(1, 1);
    load_x(0);
    sts_x();
    if (nIter > 1) asm volatile("cp.async.wait_group 1;");
    else           asm volatile("cp.async.wait_group 0;");
    __syncthreads();

    for (int it = 0; it < nIter; ++it) {
        int p = it & 1;
        if (it + 1 < nIter) load_x(it + 1);   // prefetch into regs during compute

#pragma unroll
        for (int c = 0; c < CC; c++) {
#pragma unroll
            for (int k = 0; k < K; k++) {
                u64 wv0 = *(const u64*)&swt[p][c * K + k][og * 4];
                u64 wv1 = *(const u64*)&swt[p][c * K + k][og * 4 + 2];
#pragma unroll
                for (int j = 0; j < 8; j++) {
                    u64 xv = sxd[c][tg + 16 * j + k];
                    FMA_F32X2(acc[0][j], wv0, xv, acc[0][j]);
                    FMA_F32X2(acc[1][j], wv1, xv, acc[1][j]);
                }
            }
        }
        __syncthreads();   // everyone done reading sxd / swt[p]

        if (it + 1 < nIter) {
            sts_x();
            if (it + 2 < nIter) load_w(it + 2, p);
            if (it + 2 < nIter) asm volatile("cp.async.wait_group 1;");
            else                asm volatile("cp.async.wait_group 0;");
            __syncthreads();
        }
    }

    // epilogue
#pragma unroll
    for (int o2 = 0; o2 < 2; o2++) {
        int oo0 = o0 + og * 4 + 2 * o2;
        float b0 = bias[oo0], b1 = bias[oo0 + 1];
        float* y0 = y + ((size_t)b * Cout + oo0) * TLEN + t0;
        float* y1 = y + ((size_t)b * Cout + oo0 + 1) * TLEN + t0;
#pragma unroll
        for (int j = 0; j < 8; j++) {
            float lo, hi;
            UNPACK_F32X2F(lo, hi, acc[o2][j]);
            lo += b0; hi += b1;
            if (DO_ELU) {
                lo = (lo > 0.f) ? lo : expm1f(lo);
                hi = (hi > 0.f) ? hi : expm1f(hi);
            }
            y0[tg + 16 * j] = lo;
            y1[tg + 16 * j] = hi;
        }
    }
}

// ---------------- codebook norms ----------------
__global__ void cnorm_k(const float* __restrict__ cb)
{
    int i = blockIdx.x * 256 + threadIdx.x;
    const float4* c4 = (const float4*)(cb + (size_t)i * DGRP);
    float s = 0.f;
#pragma unroll
    for (int j = 0; j < 16; j++) {
        float4 v = c4[j];
        s += v.x * v.x + v.y * v.y + v.z * v.z + v.w * v.w;
    }
    g_cnorm[i] = s;
}

// ---------------- precompute per-code head logits ----------------
__global__ void pc_k(const float* __restrict__ cb, const float* __restrict__ hw)
{
    __shared__ float sc[DGRP];
    int gk = blockIdx.x;
    int g = gk >> 10;
    int tid = threadIdx.x;
    if (tid < DGRP) sc[tid] = cb[(size_t)gk * DGRP + tid];
    __syncthreads();
    int h = tid >> 6, v = tid & 63;
    const float* wp = hw + (size_t)h * DMODEL * 64 + (size_t)(g * DGRP) * 64 + v;
    float acc = 0.f;
#pragma unroll
    for (int d = 0; d < DGRP; d++) acc += sc[d] * wp[d * 64];
    g_pc[(size_t)gk * 256 + tid] = acc;
}

// ---------------- VQ as tiled GEMM: 32 t x 1024 codes x 64 d ----------------
// Block: 256 threads = 8 warps. Warp w owns timesteps {4w..4w+3}; lane = code-slot.
// Codebook staged in smem TRANSPOSED: scT[dim_pair][code] (conflict-free).
__global__ void __launch_bounds__(256, 3)
vq_k(const float* __restrict__ x5, const float* __restrict__ cb,
     float* __restrict__ outA)
{
    constexpr int CT = 128;                    // codes per tile
    __shared__ float sz[32][66];               // [t][d], padded rows
    __shared__ u64   scT[32][CT];              // [d-pair][code], 32KB
    __shared__ float swsum[8];

    int tid = threadIdx.x;
    int t0 = blockIdx.x * 32;
    int g  = blockIdx.y;
    int b  = blockIdx.z;
    int tq = tid >> 5;                         // warp id = t-quad
    int cq = tid & 31;                         // lane = code slot

    // stage z
    const float* xp = x5 + ((size_t)b * DMODEL + g * DGRP) * TLEN + t0;
    for (int i = tid; i < 32 * DGRP; i += 256) {
        int d = i >> 5, tt = i & 31;
        sz[tt][d] = xp[(size_t)d * TLEN + tt];
    }

    const float* cbg = cb + (size_t)g * NCODE * DGRP;
    const float* cn  = g_cnorm + g * NCODE;

    float best[4];
    int   bidx[4];
#pragma unroll
    for (int i = 0; i < 4; i++) { best[i] = 3.0e38f; bidx[i] = 0; }

    int c0 = tid >> 1, half = tid & 1;         // staging role

    for (int tile = 0; tile < NCODE / CT; tile++) {
        __syncthreads();                       // prev tile fully consumed (also covers z on tile 0)
        {
            const ulonglong2* src =
                (const ulonglong2*)(cbg + (size_t)(tile * CT + c0) * DGRP + half * 32);
#pragma unroll
            for (int i = 0; i < 8; i++) {
                ulonglong2 v = src[i];
                scT[half * 16 + 2 * i][c0]     = v.x;
                scT[half * 16 + 2 * i + 1][c0] = v.y;
            }
        }
        __syncthreads();

        u64 acc[4][4];
#pragma unroll
        for (int i = 0; i < 4; i++)
#pragma unroll
            for (int j = 0; j < 4; j++) acc[i][j] = 0ull;

#pragma unroll 8
        for (int dp = 0; dp < 32; dp++) {
            u64 zl[4], cl[4];
#pragma unroll
            for (int i = 0; i < 4; i++) zl[i] = *(const u64*)&sz[tq * 4 + i][2 * dp];
#pragma unroll
            for (int j = 0; j < 4; j++) cl[j] = scT[dp][cq + 32 * j];
#pragma unroll
            for (int i = 0; i < 4; i++)
#pragma unroll
                for (int j = 0; j < 4; j++)
                    FMA_F32X2(acc[i][j], zl[i], cl[j], acc[i][j]);
        }

        // distances + argmin (codes ascend with j, so strict < keeps lowest idx)
#pragma unroll
        for (int j = 0; j < 4; j++) {
            int k = tile * CT + 32 * j + cq;
            float cnk = cn[k];
#pragma unroll
            for (int i = 0; i < 4; i++) {
                float lo, hi;
                UNPACK_F32X2F(lo, hi, acc[i][j]);
                float dist = fmaf(-2.f, lo + hi, cnk);
                if (dist < best[i] || (dist == best[i] && k < bidx[i])) {
                    best[i] = dist; bidx[i] = k;
                }
            }
        }
    }

    // warp-level argmin reduce (each warp owns 4 timesteps)
#pragma unroll
    for (int off = 16; off; off >>= 1) {
#pragma unroll
        for (int i = 0; i < 4; i++) {
            float od = __shfl_down_sync(0xffffffffu, best[i], off);
            int   oi = __shfl_down_sync(0xffffffffu, bidx[i], off);
            if (od < best[i] || (od == best[i] && oi < bidx[i])) {
                best[i] = od; bidx[i] = oi;
            }
        }
    }

    if (cq == 0) {
        float msum = 0.f;
#pragma unroll
        for (int i = 0; i < 4; i++) {
            int t = tq * 4 + i;
            size_t ai = ((size_t)b * NGRP + g) * TLEN + t0 + t;
            g_idx[ai] = bidx[i];
            outA[ai] = (float)bidx[i];
            float zn = 0.f;
            const float2* zr = (const float2*)sz[t];
#pragma unroll
            for (int d2 = 0; d2 < 32; d2++) {
                float2 v = zr[d2];
                zn += v.x * v.x + v.y * v.y;
            }
            msum += zn + best[i];
        }
        swsum[tq] = msum;
    }
    __syncthreads();
    if (tid == 0) {
        float s = 0.f;
#pragma unroll
        for (int wv = 0; wv < 8; wv++) s += swsum[wv];
        g_vqpart[((size_t)b * NGRP + g) * (TLEN / 32) + blockIdx.x] = s;
    }
}

// ---------------- vq-loss reduce ----------------
__global__ void vqred_k(float* __restrict__ out_vq)
{
    __shared__ float sred[256];
    int tid = threadIdx.x;
    float s = 0.f;
    for (int i = tid; i < (TLEN / 32) * NGRP * BATCH; i += 256) s += g_vqpart[i];
    sred[tid] = s;
    __syncthreads();
    for (int st = 128; st; st >>= 1) {
        if (tid < st) sred[tid] += sred[tid + st];
        __syncthreads();
    }
    if (tid == 0) out_vq[0] = sred[0] * (1.f / (float)(BATCH * TLEN * DGRP));
}

// ---------------- head: gather precomputed per-code logits ----------------
__global__ void __launch_bounds__(256)
head_k(const float* __restrict__ hb, float* __restrict__ outB)
{
    constexpr int TTILE = 32;
    __shared__ int sidx[TTILE][8];
    int tid = threadIdx.x;
    int b = blockIdx.y;
    int t0 = blockIdx.x * TTILE;
    {
        int tt = tid >> 3, g = tid & 7;
        sidx[tt][g] = g_idx[((size_t)b * NGRP + g) * TLEN + t0 + tt];
    }
    __syncthreads();

    int hv = tid;
    float bias = hb[hv];
    int h = hv >> 6, v = hv & 63;
    for (int tt = 0; tt < TTILE; tt++) {
        float acc = bias;
#pragma unroll
        for (int g = 0; g < 8; g++) {
            int k = sidx[tt][g];
            acc += g_pc[((size_t)(g * NCODE + k)) * 256 + hv];
        }
        outB[(((size_t)b * 4 + h) * TLEN + (t0 + tt)) * 64 + v] = acc;
    }
}

// ---------------- launch ----------------
extern "C" void kernel_launch(void* const* d_in, const int* in_sizes, int n_in,
                              void* d_out, int out_size)
{
    const float* audio = (const float*)d_in[0];
    const float* w1 = (const float*)d_in[1];
    const float* b1 = (const float*)d_in[2];
    const float* w2 = (const float*)d_in[3];
    const float* b2 = (const float*)d_in[4];
    const float* w3 = (const float*)d_in[5];
    const float* b3 = (const float*)d_in[6];
    const float* w4 = (const float*)d_in[7];
    const float* b4 = (const float*)d_in[8];
    const float* w5 = (const float*)d_in[9];
    const float* b5 = (const float*)d_in[10];
    const float* cb = (const float*)d_in[11];
    const float* hw = (const float*)d_in[12];
    const float* hb = (const float*)d_in[13];

    float* out  = (float*)d_out;
    float* outA = out;
    float* outB = out + (size_t)BATCH * NGRP * TLEN;
    float* outV = outB + (size_t)BATCH * 4 * TLEN * 64;

    cnorm_k<<<NGRP * NCODE / 256, 256>>>(cb);
    pc_k<<<NGRP * NCODE, 256>>>(cb, hw);

    conv1_k<<<dim3(TLEN / 256, BATCH), 256>>>(audio, w1, b1, g_x1);
    conv_k<5, 1><<<dim3(TLEN / 128, 2, BATCH), 256>>>(g_x1, w2, b2, g_x2, 64, 128);
    conv_k<5, 1><<<dim3(TLEN / 128, 4, BATCH), 256>>>(g_x2, w3, b3, g_x3, 128, 256);
    conv_k<3, 1><<<dim3(TLEN / 128, 8, BATCH), 256>>>(g_x3, w4, b4, g_x4, 256, 512);
    conv_k<3, 0><<<dim3(TLEN / 128, 8, BATCH), 256>>>(g_x4, w5, b5, g_x5, 512, 512);

    vq_k<<<dim3(TLEN / 32, NGRP, BATCH), 256>>>(g_x5, cb, outA);
    vqred_k<<<1, 256>>>(outV);
    head_k<<<dim3(TLEN / 32, BATCH), 256>>>(hb, outB);
}